// round 4
// baseline (speedup 1.0000x reference)
#include <cuda_runtime.h>
#include <math.h>
#include <stdint.h>

#define BB  256
#define NN  1024
#define C1  101
#define DD  256
#define HH  16
#define NEGV (-1000000000.0f)

__device__ __align__(16) float g_uv[BB * DD];
__device__ __align__(16) float g_uvc[BB * DD];
__device__ __align__(16) float g_u[BB * HH * DD];     // u[b][h][d]
__device__ __align__(16) float g_w[BB * HH * DD];     // attention-weighted ce per head
__device__ __align__(16) float g_tv[BB * DD];         // Wks^T applied glimpse-out
__device__ __align__(16) float g_part[2 * BB * 4 * DD];
__device__ int g_cnt[2 * BB * 4];

__device__ __forceinline__ bool readb(const void* p, int idx, int mode) {
    if (mode == 0) return ((const unsigned char*)p)[idx] != 0;
    if (mode == 1) return ((const int*)p)[idx] != 0;
    return ((const float*)p)[idx] != 0.0f;
}

__device__ __forceinline__ float dot4(float4 a, float4 b) {
    return a.x * b.x + a.y * b.y + a.z * b.z + a.w * b.w;
}

__device__ __forceinline__ unsigned long long pack2(float x) {
    unsigned long long r;
    asm("mov.b64 %0, {%1, %1};" : "=l"(r) : "f"(x));
    return r;
}
__device__ __forceinline__ void fma2(unsigned long long& acc, unsigned long long a,
                                     unsigned long long b) {
    asm("fma.rn.f32x2 %0, %1, %2, %0;" : "+l"(acc) : "l"(a), "l"(b));
}
union U64F2 { unsigned long long u; float2 f; };

// bool-dtype probe on first 4KB of `mask`. Call from ALL threads (sync-or).
__device__ __forceinline__ int detect_mode(const void* m, int t) {
    int f32 = 0, u8 = 0;
    if (t < 256) {
        uint4 v = ((const uint4*)m)[t];
        unsigned w[4] = {v.x, v.y, v.z, v.w};
#pragma unroll
        for (int i = 0; i < 4; i++) {
            unsigned x = w[i];
            if (((x >> 24) & 0xffu) == 0x3fu || ((x >> 16) & 0xffu) == 0x3fu ||
                ((x >> 8) & 0xffu) == 0x3fu || (x & 0xffu) == 0x3fu) f32 = 1;
            if (x & 0xffffff00u) u8 = 1;
        }
    }
    int a = __syncthreads_or(f32);
    int b = __syncthreads_or(u8);
    return a ? 2 : (b ? 0 : 1);
}

// ---------------- Kernel 1a: node partial sums (1024 CTAs: batch x quarter) --
__global__ void __launch_bounds__(256) k_nodes_part(
    const float* __restrict__ node, const void* __restrict__ mask,
    const void* __restrict__ cmask)
{
    __shared__ unsigned char code[256];
    __shared__ float4 part[2][4][64];

    int q = blockIdx.x, b = blockIdx.y, t = threadIdx.x;
    int mode = detect_mode(mask, t);

    int gidx = b * NN + q * 256 + t;
    bool m  = readb(mask,  gidx, mode);
    bool mc = m | readb(cmask, gidx, mode);
    code[t] = (unsigned char)((m ? 1 : 0) | (mc ? 2 : 0));
    int c0 = __syncthreads_count(!m);
    int c1 = __syncthreads_count(!mc);

    int chunk = t >> 6, d4 = t & 63;
    const float4* np4 = (const float4*)(node + (size_t)b * NN * DD);
    float4 s0 = make_float4(0.f, 0.f, 0.f, 0.f), s1 = s0;
    int n0 = chunk * 64;
#pragma unroll 8
    for (int i = 0; i < 64; i++) {
        int n = n0 + i;
        float4 v = np4[(size_t)(q * 256 + n) * 64 + d4];
        unsigned char c = code[n];
        if (!(c & 1)) { s0.x += v.x; s0.y += v.y; s0.z += v.z; s0.w += v.w; }
        if (!(c & 2)) { s1.x += v.x; s1.y += v.y; s1.z += v.z; s1.w += v.w; }
    }
    part[0][chunk][d4] = s0;
    part[1][chunk][d4] = s1;
    __syncthreads();

    if (t < 128) {
        int which = t >> 6, d = t & 63;
        float4 r = make_float4(0.f, 0.f, 0.f, 0.f);
#pragma unroll
        for (int c = 0; c < 4; c++) {
            float4 a = part[which][c][d];
            r.x += a.x; r.y += a.y; r.z += a.z; r.w += a.w;
        }
        ((float4*)g_part)[((which * BB + b) * 4 + q) * 64 + d] = r;
    }
    if (t == 0) {
        g_cnt[(0 * BB + b) * 4 + q] = c0;
        g_cnt[(1 * BB + b) * 4 + q] = c1;
    }
}

// ---------------- Kernel 1b: reduce partials -> uv / uvc ---------------------
__global__ void __launch_bounds__(128) k_red() {
    int b = blockIdx.x, t = threadIdx.x;
    int which = t >> 6, d = t & 63;
    float4 r = make_float4(0.f, 0.f, 0.f, 0.f);
    int cnt = 0;
#pragma unroll
    for (int q = 0; q < 4; q++) {
        float4 a = ((const float4*)g_part)[((which * BB + b) * 4 + q) * 64 + d];
        r.x += a.x; r.y += a.y; r.z += a.z; r.w += a.w;
        cnt += g_cnt[(which * BB + b) * 4 + q];
    }
    float den = fmaxf((float)cnt, 1.0f);
    r.x /= den; r.y /= den; r.z /= den; r.w /= den;
    float* dst = which ? g_uvc : g_uv;
    ((float4*)(dst + (size_t)b * DD))[d] = r;
}

// ---------------- Kernel 2: q + u (warp-per-k-chunk, batches share loads) ----
__global__ void __launch_bounds__(256) k_qu(
    const float* __restrict__ cur, const float* __restrict__ depot,
    const float* __restrict__ Wq, const float* __restrict__ Wk)
{
    __shared__ __align__(16) float ctx_s[8][768];
    __shared__ __align__(16) float qp[8][8][32];
    __shared__ __align__(16) float q_s[8][32];

    int cx = blockIdx.x;     // 0..7 : 32-col slice = 2 heads
    int by = blockIdx.y;     // 0..31: 8 batches
    int t = threadIdx.x, lane = t & 31, w = t >> 5;

    for (int i = t; i < 8 * 256; i += 256) {
        int bi = i >> 8, d = i & 255;
        int b = by * 8 + bi;
        ctx_s[bi][d]       = g_uv[(size_t)b * DD + d];
        ctx_s[bi][256 + d] = cur[(size_t)b * DD + d];
        ctx_s[bi][512 + d] = depot[(size_t)b * DD + d];
    }
    __syncthreads();

    // each warp owns 96 consecutive k's; Wq slice read ONCE per CTA
    {
        int c = cx * 32 + lane;
        float acc[8];
#pragma unroll
        for (int bi = 0; bi < 8; bi++) acc[bi] = 0.f;
        int k0 = w * 96;
        for (int k = k0; k < k0 + 96; k += 4) {
            float w0 = Wq[(size_t)(k + 0) * 256 + c];
            float w1 = Wq[(size_t)(k + 1) * 256 + c];
            float w2 = Wq[(size_t)(k + 2) * 256 + c];
            float w3 = Wq[(size_t)(k + 3) * 256 + c];
#pragma unroll
            for (int bi = 0; bi < 8; bi++) {
                acc[bi] += w0 * ctx_s[bi][k] + w1 * ctx_s[bi][k + 1]
                         + w2 * ctx_s[bi][k + 2] + w3 * ctx_s[bi][k + 3];
            }
        }
#pragma unroll
        for (int bi = 0; bi < 8; bi++) qp[w][bi][lane] = acc[bi];
    }
    __syncthreads();

    {   // reduce 8 warp-partials; warp w' handles batch w'
        int bi = w;
        float s = 0.f;
#pragma unroll
        for (int ww = 0; ww < 8; ww++) s += qp[ww][bi][lane];
        q_s[bi][lane] = s;
    }
    __syncthreads();

    // u for heads cx*2, cx*2+1; thread t = d
    int d = t;
    const float4* wk = (const float4*)(Wk + (size_t)d * 256 + cx * 32);
#pragma unroll
    for (int hl = 0; hl < 2; hl++) {
        float4 w0 = wk[hl * 4], w1 = wk[hl * 4 + 1], w2 = wk[hl * 4 + 2], w3 = wk[hl * 4 + 3];
#pragma unroll
        for (int bi = 0; bi < 8; bi++) {
            const float4* qv = (const float4*)(&q_s[bi][hl * 16]);
            float s = dot4(w0, qv[0]) + dot4(w1, qv[1]) + dot4(w2, qv[2]) + dot4(w3, qv[3]);
            g_u[(size_t)(by * 8 + bi) * (HH * DD) + (cx * 2 + hl) * 256 + d] = s;
        }
    }
}

// ---------------- Kernel 3: attention (scores, softmax, weighted sum) --------
// warp = (head-group of 4, j-half). ce rows read 2x per pass (was 8x).
__global__ void __launch_bounds__(256, 4) k_att(
    const float* __restrict__ clus, const void* __restrict__ vmask,
    const void* __restrict__ mask)
{
    __shared__ __align__(16) float att[HH * C1 + 11];   // 1627
    __shared__ __align__(16) float wpart[HH * DD];      // 16KB (jg=1 partials)
    __shared__ int vmi[C1 + 3];

    int b = blockIdx.x, t = threadIdx.x;
    int lane = t & 31, warp = t >> 5;
    int hg = warp & 3, jg = warp >> 2;
    int jbeg = jg ? 51 : 0, jend = jg ? 101 : 51;

    int mode = detect_mode(mask, t);
    if (t < C1) vmi[t] = readb(vmask, b * C1 + t, mode) ? 1 : 0;
    __syncthreads();
    if (t == 0) {
        int all = 1;
        for (int j = 1; j < C1; j++) all &= vmi[j];
        vmi[0] = !all;
    }
    __syncthreads();

    const float4* ce4r = (const float4*)(clus + (size_t)b * C1 * DD);
    const float4* up = (const float4*)(g_u + (size_t)b * (HH * DD));

    // u for 4 heads in registers
    float4 ua[4], ub[4];
#pragma unroll
    for (int h = 0; h < 4; h++) {
        ua[h] = up[(hg * 4 + h) * 64 + lane * 2];
        ub[h] = up[(hg * 4 + h) * 64 + lane * 2 + 1];
    }

    // scores
    for (int j = jbeg; j < jend; j++) {
        float4 c0 = ce4r[j * 64 + lane * 2], c1 = ce4r[j * 64 + lane * 2 + 1];
        float p0 = dot4(ua[0], c0) + dot4(ub[0], c1);
        float p1 = dot4(ua[1], c0) + dot4(ub[1], c1);
        float p2 = dot4(ua[2], c0) + dot4(ub[2], c1);
        float p3 = dot4(ua[3], c0) + dot4(ub[3], c1);
#pragma unroll
        for (int o = 16; o; o >>= 1) {
            p0 += __shfl_xor_sync(0xffffffffu, p0, o);
            p1 += __shfl_xor_sync(0xffffffffu, p1, o);
            p2 += __shfl_xor_sync(0xffffffffu, p2, o);
            p3 += __shfl_xor_sync(0xffffffffu, p3, o);
        }
        if (lane == 0) {
            int msk = vmi[j];
            att[(hg * 4 + 0) * C1 + j] = msk ? NEGV : p0 * 0.25f;
            att[(hg * 4 + 1) * C1 + j] = msk ? NEGV : p1 * 0.25f;
            att[(hg * 4 + 2) * C1 + j] = msk ? NEGV : p2 * 0.25f;
            att[(hg * 4 + 3) * C1 + j] = msk ? NEGV : p3 * 0.25f;
        }
    }
    __syncthreads();

    // softmax per head (warp w: heads w and w+8)
#pragma unroll
    for (int hh = 0; hh < 2; hh++) {
        int h = warp + 8 * hh;
        float v[4];
#pragma unroll
        for (int k = 0; k < 4; k++) {
            int j = lane + 32 * k;
            v[k] = (j < C1) ? att[h * C1 + j] : -3.0e38f;
        }
        float m = fmaxf(fmaxf(v[0], v[1]), fmaxf(v[2], v[3]));
#pragma unroll
        for (int o = 16; o; o >>= 1) m = fmaxf(m, __shfl_xor_sync(0xffffffffu, m, o));
        float e[4], s = 0.f;
#pragma unroll
        for (int k = 0; k < 4; k++) {
            int j = lane + 32 * k;
            e[k] = (j < C1) ? expf(v[k] - m) : 0.f;
            s += e[k];
        }
#pragma unroll
        for (int o = 16; o; o >>= 1) s += __shfl_xor_sync(0xffffffffu, s, o);
        float inv = 1.0f / s;
#pragma unroll
        for (int k = 0; k < 4; k++) {
            int j = lane + 32 * k;
            if (j < C1) att[h * C1 + j] = e[k] * inv;
        }
    }
    __syncthreads();

    // weighted sum: w_h[d] = sum_j attn(h,j) ce[j][d]  — f32x2 packed FMA
    {
        unsigned long long A[4][4];
#pragma unroll
        for (int h = 0; h < 4; h++)
#pragma unroll
            for (int i = 0; i < 4; i++) A[h][i] = 0ull;

        const ulonglong2* ce2 = (const ulonglong2*)ce4r;
        for (int j = jbeg; j < jend; j++) {
            ulonglong2 r0 = ce2[j * 64 + lane * 2];
            ulonglong2 r1 = ce2[j * 64 + lane * 2 + 1];
#pragma unroll
            for (int h = 0; h < 4; h++) {
                unsigned long long s = pack2(att[(hg * 4 + h) * C1 + j]);
                fma2(A[h][0], s, r0.x);
                fma2(A[h][1], s, r0.y);
                fma2(A[h][2], s, r1.x);
                fma2(A[h][3], s, r1.y);
            }
        }
        if (jg == 1) {
            float2* wp2 = (float2*)wpart;
#pragma unroll
            for (int h = 0; h < 4; h++) {
                int base = ((hg * 4 + h) * 256) / 2 + lane * 4;
#pragma unroll
                for (int i = 0; i < 4; i++) {
                    U64F2 u; u.u = A[h][i];
                    wp2[base + i] = u.f;
                }
            }
        }
        __syncthreads();
        if (jg == 0) {
            const float2* wp2 = (const float2*)wpart;
            float2* gw2 = (float2*)(g_w + (size_t)b * (HH * DD));
#pragma unroll
            for (int h = 0; h < 4; h++) {
                int base = ((hg * 4 + h) * 256) / 2 + lane * 4;
#pragma unroll
                for (int i = 0; i < 4; i++) {
                    U64F2 u; u.u = A[h][i];
                    float2 p = wp2[base + i];
                    float2 r; r.x = u.f.x + p.x; r.y = u.f.y + p.y;
                    gw2[base + i] = r;
                }
            }
        }
    }
}

// ---------------- Kernel 4: glimpse weight chain, 4 batches per CTA ----------
__global__ void __launch_bounds__(256) k_gl(
    const float* __restrict__ Wv, const float* __restrict__ Wo,
    const float* __restrict__ Wks)
{
    extern __shared__ float sm[];
    float* w_sh  = sm;              // 4 * 4096
    float* gl_sh = sm + 16384;      // 4 * 256
    float* go_sh = sm + 17408;      // 4 * 256

    int t = threadIdx.x;
    int bb0 = blockIdx.x * 4;

    {   // load w for 4 batches (64 KB)
        const float4* src = (const float4*)(g_w + (size_t)bb0 * (HH * DD));
        float4* dst = (float4*)w_sh;
        for (int i = t; i < 4096; i += 256) dst[i] = src[i];
    }
    __syncthreads();

    // gl[bi][c] = sum_d Wv[d,c] * w[bi][c>>4][d]
    {
        int c = t, hbase = (c >> 4) * 256;
        float a0 = 0.f, a1 = 0.f, a2 = 0.f, a3 = 0.f;
#pragma unroll 8
        for (int d = 0; d < 256; d++) {
            float wv = Wv[(size_t)d * 256 + c];
            a0 += wv * w_sh[0 * 4096 + hbase + d];
            a1 += wv * w_sh[1 * 4096 + hbase + d];
            a2 += wv * w_sh[2 * 4096 + hbase + d];
            a3 += wv * w_sh[3 * 4096 + hbase + d];
        }
        gl_sh[0 * 256 + c] = a0; gl_sh[1 * 256 + c] = a1;
        gl_sh[2 * 256 + c] = a2; gl_sh[3 * 256 + c] = a3;
    }
    __syncthreads();

    // go[bi][c] = sum_d gl[bi][d] * Wo[d,c]
    {
        int c = t;
        float a0 = 0.f, a1 = 0.f, a2 = 0.f, a3 = 0.f;
#pragma unroll 8
        for (int d = 0; d < 256; d++) {
            float wv = Wo[(size_t)d * 256 + c];
            a0 += wv * gl_sh[0 * 256 + d];
            a1 += wv * gl_sh[1 * 256 + d];
            a2 += wv * gl_sh[2 * 256 + d];
            a3 += wv * gl_sh[3 * 256 + d];
        }
        go_sh[0 * 256 + c] = a0; go_sh[1 * 256 + c] = a1;
        go_sh[2 * 256 + c] = a2; go_sh[3 * 256 + c] = a3;
    }
    __syncthreads();

    // tv[bi][d] = sum_c Wks[d,c] * go[bi][c]  (row-major coalesced float4)
    {
        int d = t;
        const float4* wr = (const float4*)(Wks + (size_t)d * 256);
        float a[4] = {0.f, 0.f, 0.f, 0.f};
#pragma unroll 8
        for (int c4 = 0; c4 < 64; c4++) {
            float4 wv = wr[c4];
#pragma unroll
            for (int bi = 0; bi < 4; bi++) {
                float4 g = ((const float4*)(go_sh + bi * 256))[c4];
                a[bi] += dot4(wv, g);
            }
        }
#pragma unroll
        for (int bi = 0; bi < 4; bi++)
            g_tv[(size_t)(bb0 + bi) * 256 + d] = a[bi];
    }
}

// ---------------- Kernel 5: logits, log_softmax, argmax, outputs -------------
__global__ void __launch_bounds__(256) k_out(
    const float* __restrict__ depot, const float* __restrict__ clus,
    const float* __restrict__ cur,   const void*  __restrict__ vmask,
    const void*  __restrict__ mask,  float* __restrict__ out)
{
    __shared__ float lg[C1 + 3];
    __shared__ float red[4];
    __shared__ int vmi[C1 + 3];
    __shared__ int seli[1];

    int b = blockIdx.x, t = threadIdx.x;
    int lane = t & 31, warp = t >> 5;

    int mode = detect_mode(mask, t);
    if (t < C1) vmi[t] = readb(vmask, b * C1 + t, mode) ? 1 : 0;
    __syncthreads();
    if (t == 0) {
        int all = 1;
        for (int j = 1; j < C1; j++) all &= vmi[j];
        vmi[0] = !all;
    }
    __syncthreads();

    const float4* ce4r = (const float4*)(clus + (size_t)b * C1 * DD);
    const float4* tv4 = (const float4*)(g_tv + (size_t)b * 256);
    float4 t0 = tv4[lane * 2], t1 = tv4[lane * 2 + 1];

    for (int j = warp; j < C1; j += 8) {
        float4 c0 = ce4r[j * 64 + lane * 2], c1 = ce4r[j * 64 + lane * 2 + 1];
        float s = dot4(t0, c0) + dot4(t1, c1);
#pragma unroll
        for (int o = 16; o; o >>= 1) s += __shfl_xor_sync(0xffffffffu, s, o);
        if (lane == 0) {
            float l = tanhf(s * (1.0f / 16.0f)) * 10.0f;
            lg[j] = vmi[j] ? NEGV : l;
        }
    }
    __syncthreads();

    if (warp == 0) {
        float m = -3.0e38f; int mi = 0x7fffffff;
        for (int j = lane; j < C1; j += 32) {
            float v = lg[j];
            if (v > m) { m = v; mi = j; }
        }
#pragma unroll
        for (int o = 16; o; o >>= 1) {
            float om = __shfl_xor_sync(0xffffffffu, m, o);
            int   oi = __shfl_xor_sync(0xffffffffu, mi, o);
            if (om > m || (om == m && oi < mi)) { m = om; mi = oi; }
        }
        float s = 0.f;
        for (int j = lane; j < C1; j += 32) s += expf(lg[j] - m);
#pragma unroll
        for (int o = 16; o; o >>= 1) s += __shfl_xor_sync(0xffffffffu, s, o);
        if (lane == 0) { red[0] = m + logf(s); seli[0] = mi; }
    }
    __syncthreads();

    int sel = seli[0];
    float lse = red[0];
    float se = clus[(size_t)b * C1 * DD + sel * 256 + t];
    size_t oa = (size_t)b * 1024;
    out[oa + t]       = g_uvc[(size_t)b * DD + t];
    out[oa + 256 + t] = cur[(size_t)b * DD + t];
    out[oa + 512 + t] = se;
    out[oa + 768 + t] = depot[(size_t)b * DD + t];
    out[262144 + (size_t)b * 256 + t] = se;
    if (t == 0) out[327680 + b] = (float)sel;
    if (t < C1) out[327936 + (size_t)b * C1 + t] = lg[t] - lse;
}

extern "C" void kernel_launch(void* const* d_in, const int* in_sizes, int n_in,
                              void* d_out, int out_size) {
    const float* depot = (const float*)d_in[0];
    const float* clus  = (const float*)d_in[1];
    const float* cur   = (const float*)d_in[2];
    const float* node  = (const float*)d_in[3];
    const void*  mask  = d_in[4];
    const void*  cmask = d_in[5];
    const void*  vmask = d_in[6];
    const float* Wq    = (const float*)d_in[7];
    const float* Wk    = (const float*)d_in[8];
    const float* Wv    = (const float*)d_in[9];
    const float* Wks   = (const float*)d_in[10];
    const float* Wo    = (const float*)d_in[11];
    float* out = (float*)d_out;

    static int smem_set = 0;
    if (!smem_set) {
        cudaFuncSetAttribute(k_gl, cudaFuncAttributeMaxDynamicSharedMemorySize, 73728);
        smem_set = 1;
    }

    k_nodes_part<<<dim3(4, BB), 256>>>(node, mask, cmask);
    k_red<<<BB, 128>>>();
    k_qu<<<dim3(8, 32), 256>>>(cur, depot, Wq, Wk);
    k_att<<<BB, 256>>>(clus, vmask, mask);
    k_gl<<<64, 256, 73728>>>(Wv, Wo, Wks);
    k_out<<<BB, 256>>>(depot, clus, cur, vmask, mask, out);
}

// round 5
// speedup vs baseline: 1.5297x; 1.5297x over previous
#include <cuda_runtime.h>
#include <math.h>
#include <stdint.h>

#define BB  256
#define NN  1024
#define C1  101
#define DD  256
#define HH  16
#define NEGV (-1000000000.0f)
#define AS  104          // att row stride (padded)
#define WS  260          // w_s row stride (padded, 16B-aligned, bank-skewed)

__device__ __align__(16) float g_uv[BB * DD];
__device__ __align__(16) float g_uvc[BB * DD];
__device__ __align__(16) float g_u[BB * HH * DD];     // u[b][h][d]
__device__ __align__(16) float g_part[2 * BB * 4 * DD];
__device__ int g_cnt[2 * BB * 4];

__device__ __forceinline__ bool readb(const void* p, int idx, int mode) {
    if (mode == 0) return ((const unsigned char*)p)[idx] != 0;
    if (mode == 1) return ((const int*)p)[idx] != 0;
    return ((const float*)p)[idx] != 0.0f;
}

__device__ __forceinline__ float dot4(float4 a, float4 b) {
    return a.x * b.x + a.y * b.y + a.z * b.z + a.w * b.w;
}

__device__ __forceinline__ unsigned long long pack2(float x) {
    unsigned long long r;
    asm("mov.b64 %0, {%1, %1};" : "=l"(r) : "f"(x));
    return r;
}
__device__ __forceinline__ void fma2(unsigned long long& acc, unsigned long long a,
                                     unsigned long long b) {
    asm("fma.rn.f32x2 %0, %1, %2, %0;" : "+l"(acc) : "l"(a), "l"(b));
}
union U64F2 { unsigned long long u; float2 f; };

// bool-dtype probe on first 4KB of `mask`. Call from ALL threads (sync-or).
__device__ __forceinline__ int detect_mode(const void* m, int t) {
    int f32 = 0, u8 = 0;
    if (t < 256) {
        uint4 v = ((const uint4*)m)[t];
        unsigned w[4] = {v.x, v.y, v.z, v.w};
#pragma unroll
        for (int i = 0; i < 4; i++) {
            unsigned x = w[i];
            if (((x >> 24) & 0xffu) == 0x3fu || ((x >> 16) & 0xffu) == 0x3fu ||
                ((x >> 8) & 0xffu) == 0x3fu || (x & 0xffu) == 0x3fu) f32 = 1;
            if (x & 0xffffff00u) u8 = 1;
        }
    }
    int a = __syncthreads_or(f32);
    int b = __syncthreads_or(u8);
    return a ? 2 : (b ? 0 : 1);
}

// ---------------- Kernel 1a: node partial sums (1024 CTAs) -------------------
__global__ void __launch_bounds__(256) k_nodes_part(
    const float* __restrict__ node, const void* __restrict__ mask,
    const void* __restrict__ cmask)
{
    __shared__ unsigned char code[256];
    __shared__ float4 part[2][4][64];

    int q = blockIdx.x, b = blockIdx.y, t = threadIdx.x;
    int mode = detect_mode(mask, t);

    int gidx = b * NN + q * 256 + t;
    bool m  = readb(mask,  gidx, mode);
    bool mc = m | readb(cmask, gidx, mode);
    code[t] = (unsigned char)((m ? 1 : 0) | (mc ? 2 : 0));
    int c0 = __syncthreads_count(!m);
    int c1 = __syncthreads_count(!mc);

    int chunk = t >> 6, d4 = t & 63;
    const float4* np4 = (const float4*)(node + (size_t)b * NN * DD);
    float4 s0 = make_float4(0.f, 0.f, 0.f, 0.f), s1 = s0;
    int n0 = chunk * 64;
#pragma unroll 8
    for (int i = 0; i < 64; i++) {
        int n = n0 + i;
        float4 v = __ldcs(&np4[(size_t)(q * 256 + n) * 64 + d4]);
        unsigned char c = code[n];
        if (!(c & 1)) { s0.x += v.x; s0.y += v.y; s0.z += v.z; s0.w += v.w; }
        if (!(c & 2)) { s1.x += v.x; s1.y += v.y; s1.z += v.z; s1.w += v.w; }
    }
    part[0][chunk][d4] = s0;
    part[1][chunk][d4] = s1;
    __syncthreads();

    if (t < 128) {
        int which = t >> 6, d = t & 63;
        float4 r = make_float4(0.f, 0.f, 0.f, 0.f);
#pragma unroll
        for (int c = 0; c < 4; c++) {
            float4 a = part[which][c][d];
            r.x += a.x; r.y += a.y; r.z += a.z; r.w += a.w;
        }
        ((float4*)g_part)[((which * BB + b) * 4 + q) * 64 + d] = r;
    }
    if (t == 0) {
        g_cnt[(0 * BB + b) * 4 + q] = c0;
        g_cnt[(1 * BB + b) * 4 + q] = c1;
    }
}

// ---------------- Kernel 1b: reduce partials -> uv / uvc ---------------------
__global__ void __launch_bounds__(128) k_red() {
    int b = blockIdx.x, t = threadIdx.x;
    int which = t >> 6, d = t & 63;
    float4 r = make_float4(0.f, 0.f, 0.f, 0.f);
    int cnt = 0;
#pragma unroll
    for (int q = 0; q < 4; q++) {
        float4 a = ((const float4*)g_part)[((which * BB + b) * 4 + q) * 64 + d];
        r.x += a.x; r.y += a.y; r.z += a.z; r.w += a.w;
        cnt += g_cnt[(which * BB + b) * 4 + q];
    }
    float den = fmaxf((float)cnt, 1.0f);
    r.x /= den; r.y /= den; r.z /= den; r.w /= den;
    float* dst = which ? g_uvc : g_uv;
    ((float4*)(dst + (size_t)b * DD))[d] = r;
}

// ---------------- Kernel 2: q + u (warp-per-k-chunk, batches share loads) ----
__global__ void __launch_bounds__(256) k_qu(
    const float* __restrict__ cur, const float* __restrict__ depot,
    const float* __restrict__ Wq, const float* __restrict__ Wk)
{
    __shared__ __align__(16) float ctx_s[8][768];
    __shared__ __align__(16) float qp[8][8][32];
    __shared__ __align__(16) float q_s[8][32];

    int cx = blockIdx.x;     // 0..7 : 32-col slice = 2 heads
    int by = blockIdx.y;     // 0..31: 8 batches
    int t = threadIdx.x, lane = t & 31, w = t >> 5;

    for (int i = t; i < 8 * 256; i += 256) {
        int bi = i >> 8, d = i & 255;
        int b = by * 8 + bi;
        ctx_s[bi][d]       = g_uv[(size_t)b * DD + d];
        ctx_s[bi][256 + d] = cur[(size_t)b * DD + d];
        ctx_s[bi][512 + d] = depot[(size_t)b * DD + d];
    }
    __syncthreads();

    {
        int c = cx * 32 + lane;
        float acc[8];
#pragma unroll
        for (int bi = 0; bi < 8; bi++) acc[bi] = 0.f;
        int k0 = w * 96;
        for (int k = k0; k < k0 + 96; k += 4) {
            float w0 = Wq[(size_t)(k + 0) * 256 + c];
            float w1 = Wq[(size_t)(k + 1) * 256 + c];
            float w2 = Wq[(size_t)(k + 2) * 256 + c];
            float w3 = Wq[(size_t)(k + 3) * 256 + c];
#pragma unroll
            for (int bi = 0; bi < 8; bi++) {
                acc[bi] += w0 * ctx_s[bi][k] + w1 * ctx_s[bi][k + 1]
                         + w2 * ctx_s[bi][k + 2] + w3 * ctx_s[bi][k + 3];
            }
        }
#pragma unroll
        for (int bi = 0; bi < 8; bi++) qp[w][bi][lane] = acc[bi];
    }
    __syncthreads();

    {
        int bi = w;
        float s = 0.f;
#pragma unroll
        for (int ww = 0; ww < 8; ww++) s += qp[ww][bi][lane];
        q_s[bi][lane] = s;
    }
    __syncthreads();

    int d = t;
    const float4* wk = (const float4*)(Wk + (size_t)d * 256 + cx * 32);
#pragma unroll
    for (int hl = 0; hl < 2; hl++) {
        float4 w0 = wk[hl * 4], w1 = wk[hl * 4 + 1], w2 = wk[hl * 4 + 2], w3 = wk[hl * 4 + 3];
#pragma unroll
        for (int bi = 0; bi < 8; bi++) {
            const float4* qv = (const float4*)(&q_s[bi][hl * 16]);
            float s = dot4(w0, qv[0]) + dot4(w1, qv[1]) + dot4(w2, qv[2]) + dot4(w3, qv[3]);
            g_u[(size_t)(by * 8 + bi) * (HH * DD) + (cx * 2 + hl) * 256 + d] = s;
        }
    }
}

// SMEM layout (bytes)
#define OFF_CE   0
#define OFF_WS   (OFF_CE + 101 * 256 * 4)        // 103424
#define OFF_ATT  (OFF_WS + HH * WS * 4)          // +16640
#define OFF_SCR  (OFF_ATT + HH * AS * 4)         // +6656
#define OFF_GL   (OFF_SCR + 512 * 4)             // +2048
#define OFF_GO   (OFF_GL + 1024)
#define OFF_TV   (OFF_GO + 1024)
#define OFF_LG   (OFF_TV + 1024)
#define OFF_RED  (OFF_LG + 104 * 4)
#define OFF_VMI  (OFF_RED + 16)
#define OFF_SEL  (OFF_VMI + 104 * 4)
#define SMEM_BYTES (OFF_SEL + 16)

// ---------------- Kernel 3: fused per-batch chain, ce in SMEM ----------------
__global__ void __launch_bounds__(512, 1) k_main(
    const float* __restrict__ depot, const float* __restrict__ clus,
    const float* __restrict__ cur,   const void*  __restrict__ vmask,
    const void*  __restrict__ mask,
    const float* __restrict__ Wv,    const float* __restrict__ Wks,
    const float* __restrict__ Wo,    float* __restrict__ out)
{
    extern __shared__ __align__(16) char smraw[];
    float* ce   = (float*)(smraw + OFF_CE);
    float* w_s  = (float*)(smraw + OFF_WS);
    float* att  = (float*)(smraw + OFF_ATT);
    float* scr  = (float*)(smraw + OFF_SCR);
    float* gl   = (float*)(smraw + OFF_GL);
    float* go   = (float*)(smraw + OFF_GO);
    float* tv   = (float*)(smraw + OFF_TV);
    float* lg   = (float*)(smraw + OFF_LG);
    float* red  = (float*)(smraw + OFF_RED);
    int*   vmi  = (int*)(smraw + OFF_VMI);
    int*   seli = (int*)(smraw + OFF_SEL);

    int b = blockIdx.x, t = threadIdx.x;
    int lane = t & 31, warp = t >> 5;

    int mode = detect_mode(mask, t);

    // ce -> SMEM (101 KB, coalesced float4)
    {
        const float4* cg = (const float4*)(clus + (size_t)b * C1 * DD);
        float4* d4 = (float4*)ce;
        for (int i = t; i < C1 * DD / 4; i += 512) d4[i] = cg[i];
    }
    if (t < C1) vmi[t] = readb(vmask, b * C1 + t, mode) ? 1 : 0;
    __syncthreads();
    if (t == 0) {
        int all = 1;
        for (int j = 1; j < C1; j++) all &= vmi[j];
        vmi[0] = !all;
    }
    __syncthreads();

    const float4* ce4 = (const float4*)ce;
    int hg = warp & 3;       // head group: heads hg*4 .. hg*4+3
    int qq = warp >> 2;      // quarter index 0..3

    // ---- scores: warp = (hg, j-quarter); u in registers -----------------
    {
        int jbeg = qq * 26;
        int jend = (qq == 3) ? C1 : jbeg + 26;
        const float4* up = (const float4*)(g_u + (size_t)b * (HH * DD));
        float4 ua[4], ub[4];
#pragma unroll
        for (int h = 0; h < 4; h++) {
            ua[h] = up[(hg * 4 + h) * 64 + lane * 2];
            ub[h] = up[(hg * 4 + h) * 64 + lane * 2 + 1];
        }
        for (int j = jbeg; j < jend; j++) {
            float4 c0 = ce4[j * 64 + lane * 2], c1 = ce4[j * 64 + lane * 2 + 1];
            float p0 = dot4(ua[0], c0) + dot4(ub[0], c1);
            float p1 = dot4(ua[1], c0) + dot4(ub[1], c1);
            float p2 = dot4(ua[2], c0) + dot4(ub[2], c1);
            float p3 = dot4(ua[3], c0) + dot4(ub[3], c1);
#pragma unroll
            for (int o = 16; o; o >>= 1) {
                p0 += __shfl_xor_sync(0xffffffffu, p0, o);
                p1 += __shfl_xor_sync(0xffffffffu, p1, o);
                p2 += __shfl_xor_sync(0xffffffffu, p2, o);
                p3 += __shfl_xor_sync(0xffffffffu, p3, o);
            }
            if (lane == 0) {
                int msk = vmi[j];
                att[(hg * 4 + 0) * AS + j] = msk ? NEGV : p0 * 0.25f;
                att[(hg * 4 + 1) * AS + j] = msk ? NEGV : p1 * 0.25f;
                att[(hg * 4 + 2) * AS + j] = msk ? NEGV : p2 * 0.25f;
                att[(hg * 4 + 3) * AS + j] = msk ? NEGV : p3 * 0.25f;
            }
        }
    }
    __syncthreads();

    // ---- softmax: warp = head -------------------------------------------
    {
        int h = warp;
        float v[4];
#pragma unroll
        for (int k = 0; k < 4; k++) {
            int j = lane + 32 * k;
            v[k] = (j < C1) ? att[h * AS + j] : -3.0e38f;
        }
        float m = fmaxf(fmaxf(v[0], v[1]), fmaxf(v[2], v[3]));
#pragma unroll
        for (int o = 16; o; o >>= 1) m = fmaxf(m, __shfl_xor_sync(0xffffffffu, m, o));
        float e[4], s = 0.f;
#pragma unroll
        for (int k = 0; k < 4; k++) {
            int j = lane + 32 * k;
            e[k] = (j < C1) ? expf(v[k] - m) : 0.f;
            s += e[k];
        }
#pragma unroll
        for (int o = 16; o; o >>= 1) s += __shfl_xor_sync(0xffffffffu, s, o);
        float inv = 1.0f / s;
#pragma unroll
        for (int k = 0; k < 4; k++) {
            int j = lane + 32 * k;
            if (j < C1) att[h * AS + j] = e[k] * inv;
        }
    }
    __syncthreads();

    // ---- wsum: warp = (hg, d-quarter); no shuffles, f32x2 FMA ------------
    {
        int dq = qq;   // d range [dq*64, dq*64+64); lane owns float2 at d=dq*64+lane*2
        unsigned long long A0 = 0ull, A1 = 0ull, A2 = 0ull, A3 = 0ull;
        const unsigned long long* ce2 = (const unsigned long long*)ce;
        const float* a0 = att + (hg * 4 + 0) * AS;
        const float* a1 = att + (hg * 4 + 1) * AS;
        const float* a2 = att + (hg * 4 + 2) * AS;
        const float* a3 = att + (hg * 4 + 3) * AS;
        int idx = dq * 32 + lane;
        for (int j = 0; j < C1; j++) {
            unsigned long long c = ce2[j * 128 + idx];
            fma2(A0, pack2(a0[j]), c);
            fma2(A1, pack2(a1[j]), c);
            fma2(A2, pack2(a2[j]), c);
            fma2(A3, pack2(a3[j]), c);
        }
        int dbase = dq * 64 + lane * 2;
        U64F2 u0, u1, u2, u3;
        u0.u = A0; u1.u = A1; u2.u = A2; u3.u = A3;
        *(float2*)(w_s + (hg * 4 + 0) * WS + dbase) = u0.f;
        *(float2*)(w_s + (hg * 4 + 1) * WS + dbase) = u1.f;
        *(float2*)(w_s + (hg * 4 + 2) * WS + dbase) = u2.f;
        *(float2*)(w_s + (hg * 4 + 3) * WS + dbase) = u3.f;
    }
    __syncthreads();

    int c8 = t & 255, dh = t >> 8;   // dh in {0,1}

    // ---- gl[c] = sum_d Wv[d,c] * w[c>>4][d]  (d split in halves) ---------
    {
        int h = c8 >> 4;
        const float* wr = w_s + h * WS + dh * 128;
        float a = 0.f;
#pragma unroll 8
        for (int i = 0; i < 128; i++)
            a += Wv[(size_t)(dh * 128 + i) * 256 + c8] * wr[i];
        scr[dh * 256 + c8] = a;
    }
    __syncthreads();
    if (t < 256) gl[t] = scr[t] + scr[256 + t];
    __syncthreads();

    // ---- go = gl @ Wo -----------------------------------------------------
    {
        float a = 0.f;
#pragma unroll 8
        for (int i = 0; i < 128; i++)
            a += Wo[(size_t)(dh * 128 + i) * 256 + c8] * gl[dh * 128 + i];
        scr[dh * 256 + c8] = a;
    }
    __syncthreads();
    if (t < 256) go[t] = scr[t] + scr[256 + t];
    __syncthreads();

    // ---- tv[d] = sum_c Wks[d,c] * go[c]  (c split in halves) -------------
    {
        const float4* wr = (const float4*)(Wks + (size_t)c8 * 256) + dh * 32;
        const float4* gp = (const float4*)go + dh * 32;
        float a = 0.f;
#pragma unroll 8
        for (int c4 = 0; c4 < 32; c4++) a += dot4(wr[c4], gp[c4]);
        scr[dh * 256 + c8] = a;
    }
    __syncthreads();
    if (t < 256) tv[t] = scr[t] + scr[256 + t];
    __syncthreads();

    // ---- logits: warp-dot over SMEM ce ------------------------------------
    {
        const float4* tv4 = (const float4*)tv;
        float4 t0 = tv4[lane * 2], t1 = tv4[lane * 2 + 1];
        for (int j = warp; j < C1; j += 16) {
            float4 c0 = ce4[j * 64 + lane * 2], c1 = ce4[j * 64 + lane * 2 + 1];
            float s = dot4(t0, c0) + dot4(t1, c1);
#pragma unroll
            for (int o = 16; o; o >>= 1) s += __shfl_xor_sync(0xffffffffu, s, o);
            if (lane == 0) {
                float l = tanhf(s * (1.0f / 16.0f)) * 10.0f;
                lg[j] = vmi[j] ? NEGV : l;
            }
        }
    }
    __syncthreads();

    // ---- log_softmax + argmax (warp 0) ------------------------------------
    if (warp == 0) {
        float m = -3.0e38f; int mi = 0x7fffffff;
        for (int j = lane; j < C1; j += 32) {
            float v = lg[j];
            if (v > m) { m = v; mi = j; }
        }
#pragma unroll
        for (int o = 16; o; o >>= 1) {
            float om = __shfl_xor_sync(0xffffffffu, m, o);
            int   oi = __shfl_xor_sync(0xffffffffu, mi, o);
            if (om > m || (om == m && oi < mi)) { m = om; mi = oi; }
        }
        float s = 0.f;
        for (int j = lane; j < C1; j += 32) s += expf(lg[j] - m);
#pragma unroll
        for (int o = 16; o; o >>= 1) s += __shfl_xor_sync(0xffffffffu, s, o);
        if (lane == 0) { red[0] = m + logf(s); seli[0] = mi; }
    }
    __syncthreads();

    // ---- outputs -----------------------------------------------------------
    int sel = seli[0];
    float lse = red[0];
    size_t oa = (size_t)b * 1024;
    if (t < 256) {
        float se = ce[sel * 256 + t];
        out[oa + t]       = g_uvc[(size_t)b * DD + t];
        out[oa + 512 + t] = se;
        out[262144 + (size_t)b * 256 + t] = se;
    } else {
        int d = t - 256;
        out[oa + 256 + d] = cur[(size_t)b * DD + d];
        out[oa + 768 + d] = depot[(size_t)b * DD + d];
    }
    if (t == 0) out[327680 + b] = (float)sel;
    if (t < C1) out[327936 + (size_t)b * C1 + t] = lg[t] - lse;
}

extern "C" void kernel_launch(void* const* d_in, const int* in_sizes, int n_in,
                              void* d_out, int out_size) {
    const float* depot = (const float*)d_in[0];
    const float* clus  = (const float*)d_in[1];
    const float* cur   = (const float*)d_in[2];
    const float* node  = (const float*)d_in[3];
    const void*  mask  = d_in[4];
    const void*  cmask = d_in[5];
    const void*  vmask = d_in[6];
    const float* Wq    = (const float*)d_in[7];
    const float* Wk    = (const float*)d_in[8];
    const float* Wv    = (const float*)d_in[9];
    const float* Wks   = (const float*)d_in[10];
    const float* Wo    = (const float*)d_in[11];
    float* out = (float*)d_out;

    cudaFuncSetAttribute(k_main, cudaFuncAttributeMaxDynamicSharedMemorySize, SMEM_BYTES);

    k_nodes_part<<<dim3(4, BB), 256>>>(node, mask, cmask);
    k_red<<<BB, 128>>>();
    k_qu<<<dim3(8, 32), 256>>>(cur, depot, Wq, Wk);
    k_main<<<BB, 512, SMEM_BYTES>>>(depot, clus, cur, vmask, mask, Wv, Wks, Wo, out);
}

// round 6
// speedup vs baseline: 1.7518x; 1.1452x over previous
#include <cuda_runtime.h>
#include <math.h>
#include <stdint.h>

#define BB  256
#define NN  1024
#define C1  101
#define DD  256
#define HH  16
#define NEGV (-1000000000.0f)
#define AS  104          // att row stride (floats)
#define WS  260          // w_s row stride (floats)

__device__ __align__(16) float g_u[BB * HH * DD];     // u[b][h][d]
__device__ __align__(16) float g_part[2 * BB * 4 * DD];
__device__ int g_cnt[2 * BB * 4];

__device__ __forceinline__ bool readb(const void* p, int idx, int mode) {
    if (mode == 0) return ((const unsigned char*)p)[idx] != 0;
    if (mode == 1) return ((const int*)p)[idx] != 0;
    return ((const float*)p)[idx] != 0.0f;
}

__device__ __forceinline__ float dot4(float4 a, float4 b) {
    return a.x * b.x + a.y * b.y + a.z * b.z + a.w * b.w;
}

__device__ __forceinline__ unsigned long long pack2(float x) {
    unsigned long long r;
    asm("mov.b64 %0, {%1, %1};" : "=l"(r) : "f"(x));
    return r;
}
__device__ __forceinline__ void fma2(unsigned long long& acc, unsigned long long a,
                                     unsigned long long b) {
    asm("fma.rn.f32x2 %0, %1, %2, %0;" : "+l"(acc) : "l"(a), "l"(b));
}
union U64F2 { unsigned long long u; float2 f; };

// bool-dtype probe on first 4KB of `mask`. Call from ALL threads (sync-or).
__device__ __forceinline__ int detect_mode(const void* m, int t) {
    int f32 = 0, u8 = 0;
    if (t < 256) {
        uint4 v = ((const uint4*)m)[t];
        unsigned w[4] = {v.x, v.y, v.z, v.w};
#pragma unroll
        for (int i = 0; i < 4; i++) {
            unsigned x = w[i];
            if (((x >> 24) & 0xffu) == 0x3fu || ((x >> 16) & 0xffu) == 0x3fu ||
                ((x >> 8) & 0xffu) == 0x3fu || (x & 0xffu) == 0x3fu) f32 = 1;
            if (x & 0xffffff00u) u8 = 1;
        }
    }
    int a = __syncthreads_or(f32);
    int b = __syncthreads_or(u8);
    return a ? 2 : (b ? 0 : 1);
}

// ---------------- Kernel 1: node partial sums (1024 CTAs) --------------------
__global__ void __launch_bounds__(256) k_nodes_part(
    const float* __restrict__ node, const void* __restrict__ mask,
    const void* __restrict__ cmask)
{
    __shared__ unsigned char code[256];
    __shared__ float4 part[2][4][64];

    int q = blockIdx.x, b = blockIdx.y, t = threadIdx.x;
    int mode = detect_mode(mask, t);

    int gidx = b * NN + q * 256 + t;
    bool m  = readb(mask,  gidx, mode);
    bool mc = m | readb(cmask, gidx, mode);
    code[t] = (unsigned char)((m ? 1 : 0) | (mc ? 2 : 0));
    int c0 = __syncthreads_count(!m);
    int c1 = __syncthreads_count(!mc);

    int chunk = t >> 6, d4 = t & 63;
    const float4* np4 = (const float4*)(node + (size_t)b * NN * DD);
    float4 s0 = make_float4(0.f, 0.f, 0.f, 0.f), s1 = s0;
    int n0 = chunk * 64;
#pragma unroll 8
    for (int i = 0; i < 64; i++) {
        int n = n0 + i;
        float4 v = __ldcs(&np4[(size_t)(q * 256 + n) * 64 + d4]);
        unsigned char c = code[n];
        if (!(c & 1)) { s0.x += v.x; s0.y += v.y; s0.z += v.z; s0.w += v.w; }
        if (!(c & 2)) { s1.x += v.x; s1.y += v.y; s1.z += v.z; s1.w += v.w; }
    }
    part[0][chunk][d4] = s0;
    part[1][chunk][d4] = s1;
    __syncthreads();

    if (t < 128) {
        int which = t >> 6, d = t & 63;
        float4 r = make_float4(0.f, 0.f, 0.f, 0.f);
#pragma unroll
        for (int c = 0; c < 4; c++) {
            float4 a = part[which][c][d];
            r.x += a.x; r.y += a.y; r.z += a.z; r.w += a.w;
        }
        ((float4*)g_part)[((which * BB + b) * 4 + q) * 64 + d] = r;
    }
    if (t == 0) {
        g_cnt[(0 * BB + b) * 4 + q] = c0;
        g_cnt[(1 * BB + b) * 4 + q] = c1;
    }
}

// ---------------- Kernel 2: q + u (uv reduced inline from partials) ----------
__global__ void __launch_bounds__(256) k_qu(
    const float* __restrict__ cur, const float* __restrict__ depot,
    const float* __restrict__ Wq, const float* __restrict__ Wk)
{
    __shared__ __align__(16) float ctx_s[8][768];
    __shared__ __align__(16) float qp[8][8][32];
    __shared__ __align__(16) float q_s[8][32];
    __shared__ float den_s[8];

    int cx = blockIdx.x;     // 0..7 : 32-col slice = 2 heads
    int by = blockIdx.y;     // 0..31: 8 batches
    int t = threadIdx.x, lane = t & 31, w = t >> 5;

    if (t < 8) {
        int b = by * 8 + t;
        int c = g_cnt[b * 4 + 0] + g_cnt[b * 4 + 1] + g_cnt[b * 4 + 2] + g_cnt[b * 4 + 3];
        den_s[t] = fmaxf((float)c, 1.0f);
    }
    __syncthreads();

    for (int i = t; i < 8 * 256; i += 256) {
        int bi = i >> 8, d = i & 255;
        int b = by * 8 + bi;
        float s = g_part[(size_t)(b * 4 + 0) * 256 + d] + g_part[(size_t)(b * 4 + 1) * 256 + d]
                + g_part[(size_t)(b * 4 + 2) * 256 + d] + g_part[(size_t)(b * 4 + 3) * 256 + d];
        ctx_s[bi][d]       = s / den_s[bi];
        ctx_s[bi][256 + d] = cur[(size_t)b * DD + d];
        ctx_s[bi][512 + d] = depot[(size_t)b * DD + d];
    }
    __syncthreads();

    {
        int c = cx * 32 + lane;
        float acc[8];
#pragma unroll
        for (int bi = 0; bi < 8; bi++) acc[bi] = 0.f;
        int k0 = w * 96;
        for (int k = k0; k < k0 + 96; k += 4) {
            float w0 = Wq[(size_t)(k + 0) * 256 + c];
            float w1 = Wq[(size_t)(k + 1) * 256 + c];
            float w2 = Wq[(size_t)(k + 2) * 256 + c];
            float w3 = Wq[(size_t)(k + 3) * 256 + c];
#pragma unroll
            for (int bi = 0; bi < 8; bi++) {
                acc[bi] += w0 * ctx_s[bi][k] + w1 * ctx_s[bi][k + 1]
                         + w2 * ctx_s[bi][k + 2] + w3 * ctx_s[bi][k + 3];
            }
        }
#pragma unroll
        for (int bi = 0; bi < 8; bi++) qp[w][bi][lane] = acc[bi];
    }
    __syncthreads();

    {
        int bi = w;
        float s = 0.f;
#pragma unroll
        for (int ww = 0; ww < 8; ww++) s += qp[ww][bi][lane];
        q_s[bi][lane] = s;
    }
    __syncthreads();

    int d = t;
    const float4* wk = (const float4*)(Wk + (size_t)d * 256 + cx * 32);
#pragma unroll
    for (int hl = 0; hl < 2; hl++) {
        float4 w0 = wk[hl * 4], w1 = wk[hl * 4 + 1], w2 = wk[hl * 4 + 2], w3 = wk[hl * 4 + 3];
#pragma unroll
        for (int bi = 0; bi < 8; bi++) {
            const float4* qv = (const float4*)(&q_s[bi][hl * 16]);
            float s = dot4(w0, qv[0]) + dot4(w1, qv[1]) + dot4(w2, qv[2]) + dot4(w3, qv[3]);
            g_u[(size_t)(by * 8 + bi) * (HH * DD) + (cx * 2 + hl) * 256 + d] = s;
        }
    }
}

// SMEM layout (bytes). Region A holds ce; reused after wsum for w/gl/go/tv/scr.
#define OFF_A    0
#define A_BYTES  (C1 * DD * 4)                  // 103424
#define A_W      0                              // 16 * 260 * 4 = 16640
#define A_GL     16640
#define A_GO     (A_GL + 1024)
#define A_TV     (A_GO + 1024)
#define A_SCR    (A_TV + 1024)                  // 8 * 256 * 4 = 8192
#define OFF_ATT  A_BYTES                        // 16 * 104 * 4 = 6656
#define OFF_LG   (OFF_ATT + HH * AS * 4)
#define OFF_RED  (OFF_LG + 104 * 4)
#define OFF_VMI  (OFF_RED + 16)
#define OFF_SEL  (OFF_VMI + 104 * 4)
#define SMEM_BYTES (OFF_SEL + 16)               // 110944

// ---------------- Kernel 3: fused per-batch chain, occ 2 ---------------------
__global__ void __launch_bounds__(512, 2) k_main(
    const float* __restrict__ depot, const float* __restrict__ clus,
    const float* __restrict__ cur,   const void*  __restrict__ vmask,
    const void*  __restrict__ mask,
    const float* __restrict__ Wv,    const float* __restrict__ Wks,
    const float* __restrict__ Wo,    float* __restrict__ out)
{
    extern __shared__ __align__(16) char smraw[];
    float* ce   = (float*)(smraw + OFF_A);
    float* w_s  = (float*)(smraw + A_W);
    float* gl   = (float*)(smraw + A_GL);
    float* go   = (float*)(smraw + A_GO);
    float* tv   = (float*)(smraw + A_TV);
    float* scr  = (float*)(smraw + A_SCR);
    float* att  = (float*)(smraw + OFF_ATT);
    float* lg   = (float*)(smraw + OFF_LG);
    float* red  = (float*)(smraw + OFF_RED);
    int*   vmi  = (int*)(smraw + OFF_VMI);
    int*   seli = (int*)(smraw + OFF_SEL);

    int b = blockIdx.x, t = threadIdx.x;
    int lane = t & 31, warp = t >> 5;

    int mode = detect_mode(mask, t);

    // ce -> SMEM
    {
        const float4* cg = (const float4*)(clus + (size_t)b * C1 * DD);
        float4* d4 = (float4*)ce;
        for (int i = t; i < C1 * DD / 4; i += 512) d4[i] = cg[i];
    }
    if (t < C1) vmi[t] = readb(vmask, b * C1 + t, mode) ? 1 : 0;
    __syncthreads();
    if (t == 0) {
        int all = 1;
        for (int j = 1; j < C1; j++) all &= vmi[j];
        vmi[0] = !all;
    }
    __syncthreads();

    const float4* ce4 = (const float4*)ce;
    int hg = warp & 3;       // head group: heads hg*4 .. hg*4+3
    int qq = warp >> 2;      // quarter index 0..3

    // ---- scores: warp = (hg, j-quarter); 2 passes of 2 heads (reg pressure) --
    {
        int jbeg = qq * 26;
        int jend = (qq == 3) ? C1 : jbeg + 26;
        const float4* up = (const float4*)(g_u + (size_t)b * (HH * DD));
#pragma unroll
        for (int pp = 0; pp < 2; pp++) {
            int ha = hg * 4 + pp * 2, hb = ha + 1;
            float4 ua0 = up[ha * 64 + lane * 2], ub0 = up[ha * 64 + lane * 2 + 1];
            float4 ua1 = up[hb * 64 + lane * 2], ub1 = up[hb * 64 + lane * 2 + 1];
            for (int j = jbeg; j < jend; j++) {
                float4 c0 = ce4[j * 64 + lane * 2], c1 = ce4[j * 64 + lane * 2 + 1];
                float p0 = dot4(ua0, c0) + dot4(ub0, c1);
                float p1 = dot4(ua1, c0) + dot4(ub1, c1);
#pragma unroll
                for (int o = 16; o; o >>= 1) {
                    p0 += __shfl_xor_sync(0xffffffffu, p0, o);
                    p1 += __shfl_xor_sync(0xffffffffu, p1, o);
                }
                if (lane == 0) {
                    int msk = vmi[j];
                    att[ha * AS + j] = msk ? NEGV : p0 * 0.25f;
                    att[hb * AS + j] = msk ? NEGV : p1 * 0.25f;
                }
            }
        }
    }
    __syncthreads();

    // ---- softmax: warp = head ----------------------------------------------
    {
        int h = warp;
        float v[4];
#pragma unroll
        for (int k = 0; k < 4; k++) {
            int j = lane + 32 * k;
            v[k] = (j < C1) ? att[h * AS + j] : -3.0e38f;
        }
        float m = fmaxf(fmaxf(v[0], v[1]), fmaxf(v[2], v[3]));
#pragma unroll
        for (int o = 16; o; o >>= 1) m = fmaxf(m, __shfl_xor_sync(0xffffffffu, m, o));
        float e[4], s = 0.f;
#pragma unroll
        for (int k = 0; k < 4; k++) {
            int j = lane + 32 * k;
            e[k] = (j < C1) ? expf(v[k] - m) : 0.f;
            s += e[k];
        }
#pragma unroll
        for (int o = 16; o; o >>= 1) s += __shfl_xor_sync(0xffffffffu, s, o);
        float inv = 1.0f / s;
#pragma unroll
        for (int k = 0; k < 4; k++) {
            int j = lane + 32 * k;
            if (j < C1) att[h * AS + j] = e[k] * inv;
        }
    }
    __syncthreads();

    // ---- wsum: warp = (hg, d-quarter); accumulators kept in regs ------------
    unsigned long long A0 = 0ull, A1 = 0ull, A2 = 0ull, A3 = 0ull;
    {
        const unsigned long long* ce2 = (const unsigned long long*)ce;
        const float* a0 = att + (hg * 4 + 0) * AS;
        const float* a1 = att + (hg * 4 + 1) * AS;
        const float* a2 = att + (hg * 4 + 2) * AS;
        const float* a3 = att + (hg * 4 + 3) * AS;
        int idx = qq * 32 + lane;
        for (int j = 0; j < C1; j++) {
            unsigned long long c = ce2[j * 128 + idx];
            fma2(A0, pack2(a0[j]), c);
            fma2(A1, pack2(a1[j]), c);
            fma2(A2, pack2(a2[j]), c);
            fma2(A3, pack2(a3[j]), c);
        }
    }
    __syncthreads();   // all reads of ce done; region A is now reusable

    {
        int dbase = qq * 64 + lane * 2;
        U64F2 u0, u1, u2, u3;
        u0.u = A0; u1.u = A1; u2.u = A2; u3.u = A3;
        *(float2*)(w_s + (hg * 4 + 0) * WS + dbase) = u0.f;
        *(float2*)(w_s + (hg * 4 + 1) * WS + dbase) = u1.f;
        *(float2*)(w_s + (hg * 4 + 2) * WS + dbase) = u2.f;
        *(float2*)(w_s + (hg * 4 + 3) * WS + dbase) = u3.f;
    }
    __syncthreads();

    int c4 = t & 63, g = t >> 6;      // thread owns cols 4c4..4c4+3, d-group g
    int h4 = c4 >> 2;                 // head of those 4 columns

    // ---- gl[c] = sum_d Wv[d,c] * w[h(c)][d]  (coalesced float4 row loads) ---
    {
        const float4* wv4 = (const float4*)Wv;
        float4 acc = make_float4(0.f, 0.f, 0.f, 0.f);
        const float* wrow = w_s + h4 * WS;
        int d0 = g * 32;
#pragma unroll 8
        for (int i = 0; i < 32; i++) {
            int d = d0 + i;
            float4 wv = wv4[(size_t)d * 64 + c4];
            float wd = wrow[d];
            acc.x += wv.x * wd; acc.y += wv.y * wd;
            acc.z += wv.z * wd; acc.w += wv.w * wd;
        }
        ((float4*)scr)[g * 64 + c4] = acc;
    }
    __syncthreads();
    if (t < 256) {
        float s = 0.f;
#pragma unroll
        for (int gg = 0; gg < 8; gg++) s += scr[gg * 256 + t];
        gl[t] = s;
    }
    __syncthreads();

    // ---- go = gl @ Wo --------------------------------------------------------
    {
        const float4* wo4 = (const float4*)Wo;
        float4 acc = make_float4(0.f, 0.f, 0.f, 0.f);
        int d0 = g * 32;
#pragma unroll 8
        for (int i = 0; i < 32; i++) {
            int d = d0 + i;
            float4 wv = wo4[(size_t)d * 64 + c4];
            float wd = gl[d];
            acc.x += wv.x * wd; acc.y += wv.y * wd;
            acc.z += wv.z * wd; acc.w += wv.w * wd;
        }
        ((float4*)scr)[g * 64 + c4] = acc;
    }
    __syncthreads();
    if (t < 256) {
        float s = 0.f;
#pragma unroll
        for (int gg = 0; gg < 8; gg++) s += scr[gg * 256 + t];
        go[t] = s;
    }
    __syncthreads();

    // ---- tv[d] = sum_c Wks[d,c] * go[c]  (warp per row, coalesced) ----------
    {
        const float4* wk4 = (const float4*)Wks;
        const float4* go4 = (const float4*)go;
        float4 gA = go4[lane], gB = go4[32 + lane];
        for (int r = warp; r < DD; r += 16) {
            float4 wA = wk4[(size_t)r * 64 + lane];
            float4 wB = wk4[(size_t)r * 64 + 32 + lane];
            float s = dot4(wA, gA) + dot4(wB, gB);
#pragma unroll
            for (int o = 16; o; o >>= 1) s += __shfl_xor_sync(0xffffffffu, s, o);
            if (lane == 0) tv[r] = s;
        }
    }
    __syncthreads();

    // ---- logits: ce re-read from gmem (L2) -----------------------------------
    {
        const float4* cg = (const float4*)(clus + (size_t)b * C1 * DD);
        const float4* tv4 = (const float4*)tv;
        float4 t0 = tv4[lane * 2], t1 = tv4[lane * 2 + 1];
        for (int j = warp; j < C1; j += 16) {
            float4 c0 = cg[j * 64 + lane * 2], c1 = cg[j * 64 + lane * 2 + 1];
            float s = dot4(t0, c0) + dot4(t1, c1);
#pragma unroll
            for (int o = 16; o; o >>= 1) s += __shfl_xor_sync(0xffffffffu, s, o);
            if (lane == 0) {
                float l = tanhf(s * (1.0f / 16.0f)) * 10.0f;
                lg[j] = vmi[j] ? NEGV : l;
            }
        }
    }
    __syncthreads();

    // ---- log_softmax + argmax (warp 0) ---------------------------------------
    if (warp == 0) {
        float m = -3.0e38f; int mi = 0x7fffffff;
        for (int j = lane; j < C1; j += 32) {
            float v = lg[j];
            if (v > m) { m = v; mi = j; }
        }
#pragma unroll
        for (int o = 16; o; o >>= 1) {
            float om = __shfl_xor_sync(0xffffffffu, m, o);
            int   oi = __shfl_xor_sync(0xffffffffu, mi, o);
            if (om > m || (om == m && oi < mi)) { m = om; mi = oi; }
        }
        float s = 0.f;
        for (int j = lane; j < C1; j += 32) s += expf(lg[j] - m);
#pragma unroll
        for (int o = 16; o; o >>= 1) s += __shfl_xor_sync(0xffffffffu, s, o);
        if (lane == 0) { red[0] = m + logf(s); seli[0] = mi; }
    }
    __syncthreads();

    // ---- outputs (uvc reduced inline from node partials) ---------------------
    int sel = seli[0];
    float lse = red[0];
    size_t oa = (size_t)b * 1024;
    if (t < 256) {
        float se = clus[(size_t)b * C1 * DD + (size_t)sel * 256 + t];
        int cb = (BB + b) * 4;
        float s = g_part[(size_t)(cb + 0) * 256 + t] + g_part[(size_t)(cb + 1) * 256 + t]
                + g_part[(size_t)(cb + 2) * 256 + t] + g_part[(size_t)(cb + 3) * 256 + t];
        float den = fmaxf((float)(g_cnt[cb] + g_cnt[cb + 1] + g_cnt[cb + 2] + g_cnt[cb + 3]), 1.0f);
        out[oa + t]       = s / den;
        out[oa + 512 + t] = se;
        out[262144 + (size_t)b * 256 + t] = se;
    } else {
        int d = t - 256;
        out[oa + 256 + d] = cur[(size_t)b * DD + d];
        out[oa + 768 + d] = depot[(size_t)b * DD + d];
    }
    if (t == 0) out[327680 + b] = (float)sel;
    if (t < C1) out[327936 + (size_t)b * C1 + t] = lg[t] - lse;
}

extern "C" void kernel_launch(void* const* d_in, const int* in_sizes, int n_in,
                              void* d_out, int out_size) {
    const float* depot = (const float*)d_in[0];
    const float* clus  = (const float*)d_in[1];
    const float* cur   = (const float*)d_in[2];
    const float* node  = (const float*)d_in[3];
    const void*  mask  = d_in[4];
    const void*  cmask = d_in[5];
    const void*  vmask = d_in[6];
    const float* Wq    = (const float*)d_in[7];
    const float* Wk    = (const float*)d_in[8];
    const float* Wv    = (const float*)d_in[9];
    const float* Wks   = (const float*)d_in[10];
    const float* Wo    = (const float*)d_in[11];
    float* out = (float*)d_out;

    cudaFuncSetAttribute(k_main, cudaFuncAttributeMaxDynamicSharedMemorySize, SMEM_BYTES);

    k_nodes_part<<<dim3(4, BB), 256>>>(node, mask, cmask);
    k_qu<<<dim3(8, 32), 256>>>(cur, depot, Wq, Wk);
    k_main<<<BB, 512, SMEM_BYTES>>>(depot, clus, cur, vmask, mask, Wv, Wks, Wo, out);
}